// round 5
// baseline (speedup 1.0000x reference)
#include <cuda_runtime.h>

// Laplacian pyramid, 5 levels, (16,3,1024,1024) fp32, edge-clamp padding.
// Fused per level: reduce (5x5 binomial, stride 2) + laplacian (fine - expand(coarse)).
// Big levels: block (8,32); each thread makes a 2x8 coarse block from 7 fine-row
// register windows (6 float4 each), stage-2 re-reads its 4x16 fine block from L1.
// Small levels: 2x4-per-thread variant (better latency shape for tiny grids).
// SMEM holds only the coarse tile + 1-halo for the 3x3 expand exchange.

#define NIMG 48  // 16 * 3

__device__ float g_g1[NIMG * 512 * 512];
__device__ float g_g2[NIMG * 256 * 256];
__device__ float g_g3[NIMG * 128 * 128];

// ---------------------------------------------------------------------------
// Big-level kernel: TC tile 64x64 coarse, block (8,32), 2 rows x 8 cols/thread
// ---------------------------------------------------------------------------
template <int Hc, int Wc>
__global__ __launch_bounds__(256) void fused_big_kernel(
    const float* __restrict__ fine,
    float* __restrict__ coarse_out,
    float* __restrict__ lap_out)
{
    constexpr int H = 2 * Hc, W = 2 * Wc;
    constexpr int TCY = 64, TCX = 64;
    __shared__ float sc[TCY + 2][TCX + 5];     // stride 69: 2-way max on stage-2 LDS

    const int gx = threadIdx.x;                // 0..7  (8 coarse cols each)
    const int iy = threadIdx.y;                // 0..31 (2 coarse rows each)
    const int tid = iy * 8 + gx;
    const int img = blockIdx.z;
    const int c0y = blockIdx.y * TCY;
    const int c0x = blockIdx.x * TCX;
    const int ci0 = c0y + 2 * iy;
    const int cj0 = c0x + 8 * gx;

    const float* fp = fine + (size_t)img * H * W;
    const bool leftE  = (cj0 == 0);
    const bool rightE = (cj0 == Wc - 8);
    const int cbase = 2 * cj0 - 4;             // float4-aligned

    const float hw0 = 0.0625f, hw1 = 0.25f, hw2 = 0.375f;
    const float hwv[5] = {hw0, hw1, hw2, hw1, hw0};

    float acc0[8] = {0.f, 0.f, 0.f, 0.f, 0.f, 0.f, 0.f, 0.f};
    float acc1[8] = {0.f, 0.f, 0.f, 0.f, 0.f, 0.f, 0.f, 0.f};

    // ---- stage 1: reduce — 7 fine rows cover both coarse rows ----
#pragma unroll
    for (int a = 0; a < 7; a++) {
        int r = 2 * ci0 - 2 + a;
        r = r < 0 ? 0 : (r >= H ? H - 1 : r);
        const float* rp = fp + (size_t)r * W;

        float buf[24];
        if (!leftE) {
            float4 q = *(const float4*)(rp + cbase);
            buf[0] = q.x; buf[1] = q.y; buf[2] = q.z; buf[3] = q.w;
        }
#pragma unroll
        for (int v = 1; v < 5; v++) {
            float4 q = *(const float4*)(rp + cbase + 4 * v);
            buf[4 * v] = q.x; buf[4 * v + 1] = q.y; buf[4 * v + 2] = q.z; buf[4 * v + 3] = q.w;
        }
        if (!rightE) {
            float4 q = *(const float4*)(rp + cbase + 20);
            buf[20] = q.x; buf[21] = q.y; buf[22] = q.z; buf[23] = q.w;
        } else {
            buf[20] = buf[19];                 // clamp col W -> W-1
        }
        if (leftE) { buf[2] = buf[4]; buf[3] = buf[4]; }   // clamp cols -2,-1 -> 0

        float hv[8];
#pragma unroll
        for (int t = 0; t < 8; t++) {
            hv[t] = fmaf(hw0, buf[2 + 2 * t] + buf[6 + 2 * t],
                    fmaf(hw1, buf[3 + 2 * t] + buf[5 + 2 * t],
                         hw2 * buf[4 + 2 * t]));
        }
        if (a < 5) {
            float w = hwv[a];
#pragma unroll
            for (int t = 0; t < 8; t++) acc0[t] = fmaf(w, hv[t], acc0[t]);
        }
        if (a >= 2) {
            float w = hwv[a - 2];
#pragma unroll
            for (int t = 0; t < 8; t++) acc1[t] = fmaf(w, hv[t], acc1[t]);
        }
    }

    // write coarse (global, vectorized) + stage into SMEM
    {
        float* cop = coarse_out + (size_t)img * Hc * Wc;
        *(float4*)(cop + (size_t)ci0 * Wc + cj0)     = make_float4(acc0[0], acc0[1], acc0[2], acc0[3]);
        *(float4*)(cop + (size_t)ci0 * Wc + cj0 + 4) = make_float4(acc0[4], acc0[5], acc0[6], acc0[7]);
        *(float4*)(cop + (size_t)(ci0 + 1) * Wc + cj0)     = make_float4(acc1[0], acc1[1], acc1[2], acc1[3]);
        *(float4*)(cop + (size_t)(ci0 + 1) * Wc + cj0 + 4) = make_float4(acc1[4], acc1[5], acc1[6], acc1[7]);
#pragma unroll
        for (int t = 0; t < 8; t++) {
            sc[2 * iy + 1][1 + 8 * gx + t] = acc0[t];
            sc[2 * iy + 2][1 + 8 * gx + t] = acc1[t];
        }
    }

    // ---- halo ring: 2*(TCX+2) + 2*TCY = 260 positions, clamped fallback ----
    for (int h = tid; h < 2 * (TCX + 2) + 2 * TCY; h += 256) {
        int srow, scol;
        if (h < TCX + 2)            { srow = 0;        scol = h; }
        else if (h < 2 * (TCX + 2)) { srow = TCY + 1;  scol = h - (TCX + 2); }
        else if (h < 2 * (TCX + 2) + TCY) { srow = h - 2 * (TCX + 2) + 1; scol = 0; }
        else                        { srow = h - (2 * (TCX + 2) + TCY) + 1; scol = TCX + 1; }

        int gci = c0y + srow - 1;
        gci = gci < 0 ? 0 : (gci >= Hc ? Hc - 1 : gci);
        int gcj = c0x + scol - 1;
        gcj = gcj < 0 ? 0 : (gcj >= Wc ? Wc - 1 : gcj);

        float a2 = 0.f;
#pragma unroll
        for (int a = 0; a < 5; a++) {
            int r = 2 * gci - 2 + a;
            r = r < 0 ? 0 : (r >= H ? H - 1 : r);
            const float* rp = fp + (size_t)r * W;
            float rs = 0.f;
#pragma unroll
            for (int b = 0; b < 5; b++) {
                int x = 2 * gcj - 2 + b;
                x = x < 0 ? 0 : (x >= W ? W - 1 : x);
                rs = fmaf(hwv[b], rp[x], rs);
            }
            a2 = fmaf(hwv[a], rs, a2);
        }
        sc[srow][scol] = a2;
    }

    __syncthreads();

    // ---- stage 2: laplacian. Coarse from SMEM; fine re-read (L1-resident). ----
    {
        float c4[4][10];
#pragma unroll
        for (int r = 0; r < 4; r++)
#pragma unroll
            for (int k = 0; k < 10; k++)
                c4[r][k] = sc[2 * iy + r][8 * gx + k];

        float* lop = lap_out + (size_t)img * H * W;

#pragma unroll
        for (int p = 0; p < 2; p++) {          // coarse row ci0 + p
            float rowE[10], rowO[10];
#pragma unroll
            for (int k = 0; k < 10; k++) {
                rowE[k] = fmaf(0.75f, c4[p + 1][k], 0.125f * (c4[p][k] + c4[p + 2][k]));
                rowO[k] = 0.5f * (c4[p + 1][k] + c4[p + 2][k]);
            }

            const size_t ftop = (size_t)(2 * (ci0 + p)) * W + (cbase + 4);  // = fine row, col 2*cj0
            const size_t fbot = ftop + W;

#pragma unroll
            for (int v = 0; v < 4; v++) {      // 4 float4 groups = 8 fine cols... 2 coarse cols per group
                // coarse cols cj0 + 2v, cj0 + 2v + 1 -> fine cols 2cj0+4v .. +3
                float oE0 = fmaf(0.75f, rowE[2 * v + 1], 0.125f * (rowE[2 * v] + rowE[2 * v + 2]));
                float oE1 = 0.5f * (rowE[2 * v + 1] + rowE[2 * v + 2]);
                float oE2 = fmaf(0.75f, rowE[2 * v + 2], 0.125f * (rowE[2 * v + 1] + rowE[2 * v + 3]));
                float oE3 = 0.5f * (rowE[2 * v + 2] + rowE[2 * v + 3]);
                float oO0 = fmaf(0.75f, rowO[2 * v + 1], 0.125f * (rowO[2 * v] + rowO[2 * v + 2]));
                float oO1 = 0.5f * (rowO[2 * v + 1] + rowO[2 * v + 2]);
                float oO2 = fmaf(0.75f, rowO[2 * v + 2], 0.125f * (rowO[2 * v + 1] + rowO[2 * v + 3]));
                float oO3 = 0.5f * (rowO[2 * v + 2] + rowO[2 * v + 3]);

                float4 fT = *(const float4*)(fp + ftop + 4 * v);
                float4 fB = *(const float4*)(fp + fbot + 4 * v);
                __stcs((float4*)(lop + ftop + 4 * v),
                       make_float4(fT.x - oE0, fT.y - oE1, fT.z - oE2, fT.w - oE3));
                __stcs((float4*)(lop + fbot + 4 * v),
                       make_float4(fB.x - oO0, fB.y - oO1, fB.z - oO2, fB.w - oO3));
            }
        }
    }
}

// ---------------------------------------------------------------------------
// Small-level kernel (levels 2,3): TC tile 32x64, block (16,16), 2x4/thread,
// fine block register-staged (proven R4 variant).
// ---------------------------------------------------------------------------
template <int Hc, int Wc>
__global__ __launch_bounds__(256) void fused_small_kernel(
    const float* __restrict__ fine,
    float* __restrict__ coarse_out,
    float* __restrict__ lap_out)
{
    constexpr int H = 2 * Hc, W = 2 * Wc;
    constexpr int TCY = 32, TCX = 64;
    __shared__ float sc[TCY + 2][TCX + 4];

    const int gx = threadIdx.x;                // 0..15
    const int iy = threadIdx.y;                // 0..15
    const int tid = iy * 16 + gx;
    const int img = blockIdx.z;
    const int c0y = blockIdx.y * TCY;
    const int c0x = blockIdx.x * TCX;
    const int ci0 = c0y + 2 * iy;
    const int cj0 = c0x + 4 * gx;

    const float* fp = fine + (size_t)img * H * W;
    const bool leftE  = (cj0 == 0);
    const bool rightE = (cj0 == Wc - 4);
    const int cbase = 2 * cj0 - 4;

    const float hw0 = 0.0625f, hw1 = 0.25f, hw2 = 0.375f;
    const float hwv[5] = {hw0, hw1, hw2, hw1, hw0};

    float acc0[4] = {0.f, 0.f, 0.f, 0.f};
    float acc1[4] = {0.f, 0.f, 0.f, 0.f};
    float sfr[4][8];

#pragma unroll
    for (int a = 0; a < 7; a++) {
        int r = 2 * ci0 - 2 + a;
        r = r < 0 ? 0 : (r >= H ? H - 1 : r);
        const float* rp = fp + (size_t)r * W;

        float buf[16];
        if (!leftE) {
            float4 q = *(const float4*)(rp + cbase);
            buf[0] = q.x; buf[1] = q.y; buf[2] = q.z; buf[3] = q.w;
        }
        {
            float4 q = *(const float4*)(rp + cbase + 4);
            buf[4] = q.x; buf[5] = q.y; buf[6] = q.z; buf[7] = q.w;
            float4 p = *(const float4*)(rp + cbase + 8);
            buf[8] = p.x; buf[9] = p.y; buf[10] = p.z; buf[11] = p.w;
        }
        if (!rightE) {
            float4 q = *(const float4*)(rp + cbase + 12);
            buf[12] = q.x; buf[13] = q.y; buf[14] = q.z; buf[15] = q.w;
        } else {
            buf[12] = buf[11];
        }
        if (leftE) { buf[2] = buf[4]; buf[3] = buf[4]; }

        float hv[4];
#pragma unroll
        for (int t = 0; t < 4; t++) {
            hv[t] = fmaf(hw0, buf[2 + 2 * t] + buf[6 + 2 * t],
                    fmaf(hw1, buf[3 + 2 * t] + buf[5 + 2 * t],
                         hw2 * buf[4 + 2 * t]));
        }
        if (a < 5) {
            float w = hwv[a];
#pragma unroll
            for (int t = 0; t < 4; t++) acc0[t] = fmaf(w, hv[t], acc0[t]);
        }
        if (a >= 2) {
            float w = hwv[a - 2];
#pragma unroll
            for (int t = 0; t < 4; t++) acc1[t] = fmaf(w, hv[t], acc1[t]);
        }
        if (a >= 2 && a < 6) {
#pragma unroll
            for (int k = 0; k < 8; k++) sfr[a - 2][k] = buf[4 + k];
        }
    }

    {
        float* cop = coarse_out + (size_t)img * Hc * Wc;
        *(float4*)(cop + (size_t)ci0 * Wc + cj0) = make_float4(acc0[0], acc0[1], acc0[2], acc0[3]);
        *(float4*)(cop + (size_t)(ci0 + 1) * Wc + cj0) = make_float4(acc1[0], acc1[1], acc1[2], acc1[3]);
#pragma unroll
        for (int t = 0; t < 4; t++) {
            sc[2 * iy + 1][1 + 4 * gx + t] = acc0[t];
            sc[2 * iy + 2][1 + 4 * gx + t] = acc1[t];
        }
    }

    if (tid < 2 * (TCX + 2) + 2 * TCY) {
        int srow, scol;
        if (tid < TCX + 2)            { srow = 0;        scol = tid; }
        else if (tid < 2 * (TCX + 2)) { srow = TCY + 1;  scol = tid - (TCX + 2); }
        else if (tid < 2 * (TCX + 2) + TCY) { srow = tid - 2 * (TCX + 2) + 1; scol = 0; }
        else                          { srow = tid - (2 * (TCX + 2) + TCY) + 1; scol = TCX + 1; }

        int gci = c0y + srow - 1;
        gci = gci < 0 ? 0 : (gci >= Hc ? Hc - 1 : gci);
        int gcj = c0x + scol - 1;
        gcj = gcj < 0 ? 0 : (gcj >= Wc ? Wc - 1 : gcj);

        float a2 = 0.f;
#pragma unroll
        for (int a = 0; a < 5; a++) {
            int r = 2 * gci - 2 + a;
            r = r < 0 ? 0 : (r >= H ? H - 1 : r);
            const float* rp = fp + (size_t)r * W;
            float rs = 0.f;
#pragma unroll
            for (int b = 0; b < 5; b++) {
                int x = 2 * gcj - 2 + b;
                x = x < 0 ? 0 : (x >= W ? W - 1 : x);
                rs = fmaf(hwv[b], rp[x], rs);
            }
            a2 = fmaf(hwv[a], rs, a2);
        }
        sc[srow][scol] = a2;
    }

    __syncthreads();

    {
        float c4[4][6];
#pragma unroll
        for (int r = 0; r < 4; r++)
#pragma unroll
            for (int k = 0; k < 6; k++)
                c4[r][k] = sc[2 * iy + r][4 * gx + k];

        float* lop = lap_out + (size_t)img * H * W;

#pragma unroll
        for (int p = 0; p < 2; p++) {
            float rowE[6], rowO[6];
#pragma unroll
            for (int k = 0; k < 6; k++) {
                rowE[k] = fmaf(0.75f, c4[p + 1][k], 0.125f * (c4[p][k] + c4[p + 2][k]));
                rowO[k] = 0.5f * (c4[p + 1][k] + c4[p + 2][k]);
            }
            float oE[8], oO[8];
#pragma unroll
            for (int t = 0; t < 4; t++) {
                oE[2 * t]     = fmaf(0.75f, rowE[t + 1], 0.125f * (rowE[t] + rowE[t + 2]));
                oE[2 * t + 1] = 0.5f * (rowE[t + 1] + rowE[t + 2]);
                oO[2 * t]     = fmaf(0.75f, rowO[t + 1], 0.125f * (rowO[t] + rowO[t + 2]));
                oO[2 * t + 1] = 0.5f * (rowO[t + 1] + rowO[t + 2]);
            }

            const float* fE = sfr[2 * p];
            const float* fO = sfr[2 * p + 1];
            size_t top = (size_t)(2 * (ci0 + p)) * W + 2 * cj0;
            size_t bot = top + W;

            __stcs((float4*)(lop + top),
                   make_float4(fE[0] - oE[0], fE[1] - oE[1], fE[2] - oE[2], fE[3] - oE[3]));
            __stcs((float4*)(lop + top + 4),
                   make_float4(fE[4] - oE[4], fE[5] - oE[5], fE[6] - oE[6], fE[7] - oE[7]));
            __stcs((float4*)(lop + bot),
                   make_float4(fO[0] - oO[0], fO[1] - oO[1], fO[2] - oO[2], fO[3] - oO[3]));
            __stcs((float4*)(lop + bot + 4),
                   make_float4(fO[4] - oO[4], fO[5] - oO[5], fO[6] - oO[6], fO[7] - oO[7]));
        }
    }
}

extern "C" void kernel_launch(void* const* d_in, const int* in_sizes, int n_in,
                              void* d_out, int out_size) {
    const float* im = (const float*)d_in[0];
    float* out = (float*)d_out;

    float* g1; float* g2; float* g3;
    cudaGetSymbolAddress((void**)&g1, g_g1);
    cudaGetSymbolAddress((void**)&g2, g_g2);
    cudaGetSymbolAddress((void**)&g3, g_g3);

    const long long off0 = 0;
    const long long off1 = off0 + (long long)NIMG * 1024 * 1024;
    const long long off2 = off1 + (long long)NIMG * 512 * 512;
    const long long off3 = off2 + (long long)NIMG * 256 * 256;
    const long long off4 = off3 + (long long)NIMG * 128 * 128;

    // level l: fine = g_l, writes g_{l+1} and lap_l
    {
        dim3 grid(512 / 64, 512 / 64, NIMG);   // coarse 512x512, tile 64x64
        fused_big_kernel<512, 512><<<grid, dim3(8, 32)>>>(im, g1, out + off0);
    }
    {
        dim3 grid(256 / 64, 256 / 64, NIMG);   // coarse 256x256
        fused_big_kernel<256, 256><<<grid, dim3(8, 32)>>>(g1, g2, out + off1);
    }
    {
        dim3 grid(128 / 64, 128 / 32, NIMG);   // coarse 128x128
        fused_small_kernel<128, 128><<<grid, dim3(16, 16)>>>(g2, g3, out + off2);
    }
    {
        dim3 grid(64 / 64, 64 / 32, NIMG);     // coarse 64x64; g4 = lpyr[4]
        fused_small_kernel<64, 64><<<grid, dim3(16, 16)>>>(g3, out + off4, out + off3);
    }
}

// round 6
// speedup vs baseline: 2.2926x; 2.2926x over previous
#include <cuda_runtime.h>

// Laplacian pyramid, 5 levels, (16,3,1024,1024) fp32, edge-clamp padding.
// Fused per level: reduce (5x5 binomial, stride 2) + laplacian (fine - expand(coarse)).
// Block (18,18): interior 16x16 threads make the 32x64 coarse tile (2x4 each);
// the border ring of threads computes the coarse halo with the SAME vectorized
// path (clamped coordinates), so there is no scalar halo fallback at all.

#define NIMG 48  // 16 * 3

__device__ float g_g1[NIMG * 512 * 512];
__device__ float g_g2[NIMG * 256 * 256];
__device__ float g_g3[NIMG * 128 * 128];

template <int Hc, int Wc>
__global__ __launch_bounds__(324) void fused_level_kernel(
    const float* __restrict__ fine,
    float* __restrict__ coarse_out,
    float* __restrict__ lap_out)
{
    constexpr int H = 2 * Hc, W = 2 * Wc;
    constexpr int TCY = 32, TCX = 64;          // inner coarse tile per CTA
    // sc row sr  <-> coarse row (c0y - 2 + sr),  sr in 0..35
    // sc col scl <-> coarse col (c0x - 4 + scl), scl in 0..71
    __shared__ float sc[36][73];

    const int gx = threadIdx.x;                // 0..17 (4 coarse cols each)
    const int iy = threadIdx.y;                // 0..17 (2 coarse rows each)
    const int img = blockIdx.z;
    const int c0y = blockIdx.y * TCY;
    const int c0x = blockIdx.x * TCX;
    const int ci0 = c0y + 2 * (iy - 1);        // may be -2 or Hc (halo threads)
    const int cj0 = c0x + 4 * (gx - 1);        // may be -4 or Wc (halo threads)

    // clamped compute coordinates
    const int ci0c = ci0 < 0 ? 0 : (ci0 > Hc - 2 ? Hc - 2 : ci0);
    const int cj0c = cj0 < 0 ? 0 : (cj0 > Wc - 4 ? Wc - 4 : cj0);
    const bool topE   = (ci0 < 0);
    const bool botE   = (ci0 > Hc - 2);
    const bool lColE  = (cj0 < 0);             // whole group clamps to coarse col 0
    const bool rColE  = (cj0 > Wc - 4);        // whole group clamps to col Wc-1

    const float* fp = fine + (size_t)img * H * W;
    const bool leftE  = (cj0c == 0);
    const bool rightE = (cj0c == Wc - 4);
    const int cbase = 2 * cj0c - 4;            // float4-aligned fine col base

    const float hw0 = 0.0625f, hw1 = 0.25f, hw2 = 0.375f;
    const float hwv[5] = {hw0, hw1, hw2, hw1, hw0};

    float acc0[4] = {0.f, 0.f, 0.f, 0.f};      // coarse row ci0c
    float acc1[4] = {0.f, 0.f, 0.f, 0.f};      // coarse row ci0c+1
    float sfr[4][8];                           // fine rows 2ci0c..+3, cols 2cj0c..+7

    // ---- stage 1: reduce — 7 fine rows cover both coarse rows ----
#pragma unroll
    for (int a = 0; a < 7; a++) {
        int r = 2 * ci0c - 2 + a;
        r = r < 0 ? 0 : (r >= H ? H - 1 : r);
        const float* rp = fp + (size_t)r * W;

        float buf[16];
        if (!leftE) {
            float4 q = *(const float4*)(rp + cbase);
            buf[0] = q.x; buf[1] = q.y; buf[2] = q.z; buf[3] = q.w;
        }
        {
            float4 q = *(const float4*)(rp + cbase + 4);
            buf[4] = q.x; buf[5] = q.y; buf[6] = q.z; buf[7] = q.w;
            float4 p = *(const float4*)(rp + cbase + 8);
            buf[8] = p.x; buf[9] = p.y; buf[10] = p.z; buf[11] = p.w;
        }
        if (!rightE) {
            float4 q = *(const float4*)(rp + cbase + 12);
            buf[12] = q.x; buf[13] = q.y; buf[14] = q.z; buf[15] = q.w;
        } else {
            buf[12] = buf[11];                 // clamp col W -> W-1
        }
        if (leftE) { buf[2] = buf[4]; buf[3] = buf[4]; }  // clamp cols -2,-1 -> 0

        float hv[4];
#pragma unroll
        for (int t = 0; t < 4; t++) {
            hv[t] = fmaf(hw0, buf[2 + 2 * t] + buf[6 + 2 * t],
                    fmaf(hw1, buf[3 + 2 * t] + buf[5 + 2 * t],
                         hw2 * buf[4 + 2 * t]));
        }
        if (a < 5) {
            float w = hwv[a];
#pragma unroll
            for (int t = 0; t < 4; t++) acc0[t] = fmaf(w, hv[t], acc0[t]);
        }
        if (a >= 2) {
            float w = hwv[a - 2];
#pragma unroll
            for (int t = 0; t < 4; t++) acc1[t] = fmaf(w, hv[t], acc1[t]);
        }
        if (a >= 2 && a < 6) {
#pragma unroll
            for (int k = 0; k < 8; k++) sfr[a - 2][k] = buf[4 + k];
        }
    }

    // column-edge groups: every stored col clamps to the same coarse col
    if (lColE) {
        acc0[1] = acc0[0]; acc0[2] = acc0[0]; acc0[3] = acc0[0];
        acc1[1] = acc1[0]; acc1[2] = acc1[0]; acc1[3] = acc1[0];
    }
    if (rColE) {
        acc0[0] = acc0[3]; acc0[1] = acc0[3]; acc0[2] = acc0[3];
        acc1[0] = acc1[3]; acc1[1] = acc1[3]; acc1[2] = acc1[3];
    }

    // stage into SMEM (row-edge threads broadcast the clamped row)
    {
        const int sr = 2 * iy, scl = 4 * gx;
#pragma unroll
        for (int t = 0; t < 4; t++) {
            float v0 = topE ? acc0[t] : (botE ? acc1[t] : acc0[t]);
            float v1 = topE ? acc0[t] : acc1[t];
            sc[sr][scl + t] = v0;
            sc[sr + 1][scl + t] = v1;
        }
    }

    const bool inner = (iy >= 1) && (iy <= 16) && (gx >= 1) && (gx <= 16);

    // write coarse level to global (inner threads only; float4)
    if (inner) {
        float* cop = coarse_out + (size_t)img * Hc * Wc;
        *(float4*)(cop + (size_t)ci0 * Wc + cj0) =
            make_float4(acc0[0], acc0[1], acc0[2], acc0[3]);
        *(float4*)(cop + (size_t)(ci0 + 1) * Wc + cj0) =
            make_float4(acc1[0], acc1[1], acc1[2], acc1[3]);
    }

    __syncthreads();

    // ---- stage 2: laplacian from SMEM coarse + register fine ----
    if (inner) {
        float c4[4][6];
#pragma unroll
        for (int r = 0; r < 4; r++)
#pragma unroll
            for (int k = 0; k < 6; k++)
                c4[r][k] = sc[(2 * iy - 1) + r][(4 * gx - 1) + k];

        float* lop = lap_out + (size_t)img * H * W;

#pragma unroll
        for (int p = 0; p < 2; p++) {          // coarse row ci0 + p
            float rowE[6], rowO[6];
#pragma unroll
            for (int k = 0; k < 6; k++) {
                rowE[k] = fmaf(0.75f, c4[p + 1][k], 0.125f * (c4[p][k] + c4[p + 2][k]));
                rowO[k] = 0.5f * (c4[p + 1][k] + c4[p + 2][k]);
            }
            float oE[8], oO[8];
#pragma unroll
            for (int t = 0; t < 4; t++) {
                oE[2 * t]     = fmaf(0.75f, rowE[t + 1], 0.125f * (rowE[t] + rowE[t + 2]));
                oE[2 * t + 1] = 0.5f * (rowE[t + 1] + rowE[t + 2]);
                oO[2 * t]     = fmaf(0.75f, rowO[t + 1], 0.125f * (rowO[t] + rowO[t + 2]));
                oO[2 * t + 1] = 0.5f * (rowO[t + 1] + rowO[t + 2]);
            }

            const float* fE = sfr[2 * p];      // fine row 2*(ci0+p)
            const float* fO = sfr[2 * p + 1];  // fine row 2*(ci0+p)+1
            size_t top = (size_t)(2 * (ci0 + p)) * W + 2 * cj0;
            size_t bot = top + W;

            __stcs((float4*)(lop + top),
                   make_float4(fE[0] - oE[0], fE[1] - oE[1], fE[2] - oE[2], fE[3] - oE[3]));
            __stcs((float4*)(lop + top + 4),
                   make_float4(fE[4] - oE[4], fE[5] - oE[5], fE[6] - oE[6], fE[7] - oE[7]));
            __stcs((float4*)(lop + bot),
                   make_float4(fO[0] - oO[0], fO[1] - oO[1], fO[2] - oO[2], fO[3] - oO[3]));
            __stcs((float4*)(lop + bot + 4),
                   make_float4(fO[4] - oO[4], fO[5] - oO[5], fO[6] - oO[6], fO[7] - oO[7]));
        }
    }
}

extern "C" void kernel_launch(void* const* d_in, const int* in_sizes, int n_in,
                              void* d_out, int out_size) {
    const float* im = (const float*)d_in[0];
    float* out = (float*)d_out;

    float* g1; float* g2; float* g3;
    cudaGetSymbolAddress((void**)&g1, g_g1);
    cudaGetSymbolAddress((void**)&g2, g_g2);
    cudaGetSymbolAddress((void**)&g3, g_g3);

    const long long off0 = 0;
    const long long off1 = off0 + (long long)NIMG * 1024 * 1024;
    const long long off2 = off1 + (long long)NIMG * 512 * 512;
    const long long off3 = off2 + (long long)NIMG * 256 * 256;
    const long long off4 = off3 + (long long)NIMG * 128 * 128;

    dim3 block(18, 18);

    // level l: fine = g_l, writes g_{l+1} and lap_l
    {
        dim3 grid(512 / 64, 512 / 32, NIMG);   // coarse 512x512
        fused_level_kernel<512, 512><<<grid, block>>>(im, g1, out + off0);
    }
    {
        dim3 grid(256 / 64, 256 / 32, NIMG);   // coarse 256x256
        fused_level_kernel<256, 256><<<grid, block>>>(g1, g2, out + off1);
    }
    {
        dim3 grid(128 / 64, 128 / 32, NIMG);   // coarse 128x128
        fused_level_kernel<128, 128><<<grid, block>>>(g2, g3, out + off2);
    }
    {
        dim3 grid(64 / 64, 64 / 32, NIMG);     // coarse 64x64; g4 = lpyr[4]
        fused_level_kernel<64, 64><<<grid, block>>>(g3, out + off4, out + off3);
    }
}

// round 8
// speedup vs baseline: 2.3858x; 1.0407x over previous
#include <cuda_runtime.h>

// Laplacian pyramid, 5 levels, (16,3,1024,1024) fp32, edge-clamp padding.
// Fused per level: reduce (5x5 binomial, stride 2) + laplacian (fine - expand(coarse)).
// Block (18, TCY/2+2): interior threads make the TCYx64 coarse tile (2x4 each);
// the border ring computes the coarse halo with the SAME vectorized path
// (clamped coordinates) — no scalar halo fallback. TCY=32 for big levels,
// TCY=16 for small levels (more CTAs -> shorter latency-bound tail).

#define NIMG 48  // 16 * 3

__device__ float g_g1[NIMG * 512 * 512];
__device__ float g_g2[NIMG * 256 * 256];
__device__ float g_g3[NIMG * 128 * 128];

template <int Hc, int Wc, int TCY>
__global__ __launch_bounds__(18 * (TCY / 2 + 2), 3) void fused_level_kernel(
    const float* __restrict__ fine,
    float* __restrict__ coarse_out,
    float* __restrict__ lap_out)
{
    constexpr int H = 2 * Hc, W = 2 * Wc;
    constexpr int TCX = 64;                    // inner coarse tile width
    constexpr int IY = TCY / 2;                // inner thread rows
    // sc row sr  <-> coarse row (c0y - 2 + sr)
    // sc col scl <-> coarse col (c0x - 4 + scl)
    __shared__ float sc[TCY + 4][73];

    const int gx = threadIdx.x;                // 0..17 (4 coarse cols each)
    const int iy = threadIdx.y;                // 0..IY+1 (2 coarse rows each)
    const int img = blockIdx.z;
    const int c0y = blockIdx.y * TCY;
    const int c0x = blockIdx.x * TCX;
    const int ci0 = c0y + 2 * (iy - 1);        // may be -2 or Hc (halo threads)
    const int cj0 = c0x + 4 * (gx - 1);        // may be -4 or Wc (halo threads)

    // clamped compute coordinates
    const int ci0c = ci0 < 0 ? 0 : (ci0 > Hc - 2 ? Hc - 2 : ci0);
    const int cj0c = cj0 < 0 ? 0 : (cj0 > Wc - 4 ? Wc - 4 : cj0);
    const bool topE   = (ci0 < 0);
    const bool botE   = (ci0 > Hc - 2);
    const bool lColE  = (cj0 < 0);             // whole group clamps to coarse col 0
    const bool rColE  = (cj0 > Wc - 4);        // whole group clamps to col Wc-1

    const float* fp = fine + (size_t)img * H * W;
    const bool leftE  = (cj0c == 0);
    const bool rightE = (cj0c == Wc - 4);
    const int cbase = 2 * cj0c - 4;            // float4-aligned fine col base

    const float hw0 = 0.0625f, hw1 = 0.25f, hw2 = 0.375f;
    const float hwv[5] = {hw0, hw1, hw2, hw1, hw0};

    float acc0[4] = {0.f, 0.f, 0.f, 0.f};      // coarse row ci0c
    float acc1[4] = {0.f, 0.f, 0.f, 0.f};      // coarse row ci0c+1
    float sfr[4][8];                           // fine rows 2ci0c..+3, cols 2cj0c..+7

    // ---- stage 1: reduce — 7 fine rows cover both coarse rows ----
#pragma unroll
    for (int a = 0; a < 7; a++) {
        int r = 2 * ci0c - 2 + a;
        r = r < 0 ? 0 : (r >= H ? H - 1 : r);
        const float* rp = fp + (size_t)r * W;

        float buf[16];
        if (!leftE) {
            float4 q = *(const float4*)(rp + cbase);
            buf[0] = q.x; buf[1] = q.y; buf[2] = q.z; buf[3] = q.w;
        }
        {
            float4 q = *(const float4*)(rp + cbase + 4);
            buf[4] = q.x; buf[5] = q.y; buf[6] = q.z; buf[7] = q.w;
            float4 p = *(const float4*)(rp + cbase + 8);
            buf[8] = p.x; buf[9] = p.y; buf[10] = p.z; buf[11] = p.w;
        }
        if (!rightE) {
            float4 q = *(const float4*)(rp + cbase + 12);
            buf[12] = q.x; buf[13] = q.y; buf[14] = q.z; buf[15] = q.w;
        } else {
            buf[12] = buf[11];                 // clamp col W -> W-1
        }
        if (leftE) { buf[2] = buf[4]; buf[3] = buf[4]; }  // clamp cols -2,-1 -> 0

        float hv[4];
#pragma unroll
        for (int t = 0; t < 4; t++) {
            hv[t] = fmaf(hw0, buf[2 + 2 * t] + buf[6 + 2 * t],
                    fmaf(hw1, buf[3 + 2 * t] + buf[5 + 2 * t],
                         hw2 * buf[4 + 2 * t]));
        }
        if (a < 5) {
            float w = hwv[a];
#pragma unroll
            for (int t = 0; t < 4; t++) acc0[t] = fmaf(w, hv[t], acc0[t]);
        }
        if (a >= 2) {
            float w = hwv[a - 2];
#pragma unroll
            for (int t = 0; t < 4; t++) acc1[t] = fmaf(w, hv[t], acc1[t]);
        }
        if (a >= 2 && a < 6) {
#pragma unroll
            for (int k = 0; k < 8; k++) sfr[a - 2][k] = buf[4 + k];
        }
    }

    // column-edge groups: every stored col clamps to the same coarse col
    if (lColE) {
        acc0[1] = acc0[0]; acc0[2] = acc0[0]; acc0[3] = acc0[0];
        acc1[1] = acc1[0]; acc1[2] = acc1[0]; acc1[3] = acc1[0];
    }
    if (rColE) {
        acc0[0] = acc0[3]; acc0[1] = acc0[3]; acc0[2] = acc0[3];
        acc1[0] = acc1[3]; acc1[1] = acc1[3]; acc1[2] = acc1[3];
    }

    // stage into SMEM (row-edge threads broadcast the clamped row)
    {
        const int sr = 2 * iy, scl = 4 * gx;
#pragma unroll
        for (int t = 0; t < 4; t++) {
            float v0 = topE ? acc0[t] : (botE ? acc1[t] : acc0[t]);
            float v1 = topE ? acc0[t] : acc1[t];
            sc[sr][scl + t] = v0;
            sc[sr + 1][scl + t] = v1;
        }
    }

    const bool inner = (iy >= 1) && (iy <= IY) && (gx >= 1) && (gx <= 16);

    // write coarse level to global (inner threads only; float4)
    if (inner) {
        float* cop = coarse_out + (size_t)img * Hc * Wc;
        *(float4*)(cop + (size_t)ci0 * Wc + cj0) =
            make_float4(acc0[0], acc0[1], acc0[2], acc0[3]);
        *(float4*)(cop + (size_t)(ci0 + 1) * Wc + cj0) =
            make_float4(acc1[0], acc1[1], acc1[2], acc1[3]);
    }

    __syncthreads();

    // ---- stage 2: laplacian from SMEM coarse + register fine ----
    if (inner) {
        float c4[4][6];
#pragma unroll
        for (int r = 0; r < 4; r++)
#pragma unroll
            for (int k = 0; k < 6; k++)
                c4[r][k] = sc[(2 * iy - 1) + r][(4 * gx - 1) + k];

        float* lop = lap_out + (size_t)img * H * W;

#pragma unroll
        for (int p = 0; p < 2; p++) {          // coarse row ci0 + p
            float rowE[6], rowO[6];
#pragma unroll
            for (int k = 0; k < 6; k++) {
                rowE[k] = fmaf(0.75f, c4[p + 1][k], 0.125f * (c4[p][k] + c4[p + 2][k]));
                rowO[k] = 0.5f * (c4[p + 1][k] + c4[p + 2][k]);
            }
            float oE[8], oO[8];
#pragma unroll
            for (int t = 0; t < 4; t++) {
                oE[2 * t]     = fmaf(0.75f, rowE[t + 1], 0.125f * (rowE[t] + rowE[t + 2]));
                oE[2 * t + 1] = 0.5f * (rowE[t + 1] + rowE[t + 2]);
                oO[2 * t]     = fmaf(0.75f, rowO[t + 1], 0.125f * (rowO[t] + rowO[t + 2]));
                oO[2 * t + 1] = 0.5f * (rowO[t + 1] + rowO[t + 2]);
            }

            const float* fE = sfr[2 * p];      // fine row 2*(ci0+p)
            const float* fO = sfr[2 * p + 1];  // fine row 2*(ci0+p)+1
            size_t top = (size_t)(2 * (ci0 + p)) * W + 2 * cj0;
            size_t bot = top + W;

            __stcs((float4*)(lop + top),
                   make_float4(fE[0] - oE[0], fE[1] - oE[1], fE[2] - oE[2], fE[3] - oE[3]));
            __stcs((float4*)(lop + top + 4),
                   make_float4(fE[4] - oE[4], fE[5] - oE[5], fE[6] - oE[6], fE[7] - oE[7]));
            __stcs((float4*)(lop + bot),
                   make_float4(fO[0] - oO[0], fO[1] - oO[1], fO[2] - oO[2], fO[3] - oO[3]));
            __stcs((float4*)(lop + bot + 4),
                   make_float4(fO[4] - oO[4], fO[5] - oO[5], fO[6] - oO[6], fO[7] - oO[7]));
        }
    }
}

extern "C" void kernel_launch(void* const* d_in, const int* in_sizes, int n_in,
                              void* d_out, int out_size) {
    const float* im = (const float*)d_in[0];
    float* out = (float*)d_out;

    float* g1; float* g2; float* g3;
    cudaGetSymbolAddress((void**)&g1, g_g1);
    cudaGetSymbolAddress((void**)&g2, g_g2);
    cudaGetSymbolAddress((void**)&g3, g_g3);

    const long long off0 = 0;
    const long long off1 = off0 + (long long)NIMG * 1024 * 1024;
    const long long off2 = off1 + (long long)NIMG * 512 * 512;
    const long long off3 = off2 + (long long)NIMG * 256 * 256;
    const long long off4 = off3 + (long long)NIMG * 128 * 128;

    // level l: fine = g_l, writes g_{l+1} and lap_l
    {
        dim3 grid(512 / 64, 512 / 32, NIMG);   // coarse 512x512, tile 32x64
        fused_level_kernel<512, 512, 32><<<grid, dim3(18, 18)>>>(im, g1, out + off0);
    }
    {
        dim3 grid(256 / 64, 256 / 32, NIMG);   // coarse 256x256
        fused_level_kernel<256, 256, 32><<<grid, dim3(18, 18)>>>(g1, g2, out + off1);
    }
    {
        dim3 grid(128 / 64, 128 / 16, NIMG);   // coarse 128x128, tile 16x64
        fused_level_kernel<128, 128, 16><<<grid, dim3(18, 10)>>>(g2, g3, out + off2);
    }
    {
        dim3 grid(64 / 64, 64 / 16, NIMG);     // coarse 64x64; g4 = lpyr[4]
        fused_level_kernel<64, 64, 16><<<grid, dim3(18, 10)>>>(g3, out + off4, out + off3);
    }
}